// round 11
// baseline (speedup 1.0000x reference)
#include <cuda_runtime.h>
#include <cuda_bf16.h>
#include <float.h>
#include <cstdint>

// Problem constants (fixed by the dataset)
#define MAX_NODES 100000
#define MAX_TOTAL 1703936   // E + n upper bound
#define D_FEAT 32
#define D_HID 64
#define D_OUT 64
#define TILE_E 64
#define H_STRIDE 68   // floats per H row (64 + pad, 16B-aligned)

// Scratch: per-node precomputed term.
// U[j] = x_j @ W1[:32] + pos_j @ W1[32:35] + b1   (N x 64)
// P[i] = pos_i @ W1[32:35] is RANK-3: computed on the fly from pos (12B/edge)
// instead of being materialized (256B/edge gather saved).
__device__ float g_U[MAX_NODES * D_HID];
__device__ int g_is64;
// Normalized edge list (int32, self-loops appended): size total = E + n.
__device__ int g_SRC[MAX_TOTAL];
__device__ int g_DST[MAX_TOTAL];

// ---------------------------------------------------------------------------
// packed fp32x2 helpers (bit-exact pair of fp32 FMAs)
// ---------------------------------------------------------------------------
__device__ __forceinline__ void ffma2(unsigned long long& d,
                                      unsigned long long a,
                                      unsigned long long b) {
    asm("fma.rn.f32x2 %0, %1, %2, %0;" : "+l"(d) : "l"(a), "l"(b));
}
__device__ __forceinline__ unsigned long long packdup(float x) {
    unsigned long long r;
    asm("mov.b64 %0, {%1, %1};" : "=l"(r) : "f"(x));
    return r;
}
__device__ __forceinline__ void unpack2(unsigned long long v, float& lo, float& hi) {
    asm("mov.b64 {%0, %1}, %2;" : "=f"(lo), "=f"(hi) : "l"(v));
}
__device__ __forceinline__ void prefetchL2(const void* p) {
    asm volatile("prefetch.global.L2 [%0];" :: "l"(p));
}

// ---------------------------------------------------------------------------
// Kernel 0: detect edge_index element width (int64 vs int32).
// ---------------------------------------------------------------------------
__global__ void detect_kernel(const long long* __restrict__ ei64, int E, int n) {
    __shared__ int bad;
    if (threadIdx.x == 0) bad = 0;
    __syncthreads();
    int samples = min(4096, E);
    for (int i = threadIdx.x; i < samples; i += blockDim.x) {
        long long v = ei64[i];
        if (v < 0 || v >= (long long)n) atomicOr(&bad, 1);
    }
    __syncthreads();
    if (threadIdx.x == 0) g_is64 = bad ? 0 : 1;
}

// ---------------------------------------------------------------------------
// Kernel 0b: normalize edge list to int32 with self-loops appended.
// ---------------------------------------------------------------------------
__global__ void convert_edges_kernel(const void* __restrict__ ei_raw,
                                     int E, int n) {
    const int is64 = g_is64;
    const long long* ei64 = (const long long*)ei_raw;
    const int*       ei32 = (const int*)ei_raw;
    const int total = E + n;
    for (int i = blockIdx.x * blockDim.x + threadIdx.x; i < total;
         i += gridDim.x * blockDim.x) {
        int s, d;
        if (i < E) {
            if (is64) { s = (int)ei64[i]; d = (int)ei64[E + i]; }
            else      { s = ei32[i];      d = ei32[E + i]; }
        } else { s = i - E; d = s; }
        g_SRC[i] = s;
        g_DST[i] = d;
    }
}

// ---------------------------------------------------------------------------
// Kernel 1: per-node precompute of U (grid-stride) + out init fused.
// ---------------------------------------------------------------------------
__global__ void precompute_kernel(const float* __restrict__ x,
                                  const float* __restrict__ pos,
                                  const float* __restrict__ W1,
                                  const float* __restrict__ b1,
                                  float* __restrict__ out,
                                  int n) {
    __shared__ float W1s[35 * 64];
    __shared__ float b1s[64];
    for (int i = threadIdx.x; i < 35 * 64; i += blockDim.x) W1s[i] = W1[i];
    if (threadIdx.x < 64) b1s[threadIdx.x] = b1[threadIdx.x];
    __syncthreads();

    const int totalW = n * 64;
    for (int gid = blockIdx.x * blockDim.x + threadIdx.x; gid < totalW;
         gid += gridDim.x * blockDim.x) {
        int node = gid >> 6;
        int k = gid & 63;

        const float* xr = x + node * D_FEAT;
        float acc = b1s[k];
#pragma unroll
        for (int f = 0; f < D_FEAT; f++) acc = fmaf(xr[f], W1s[f * 64 + k], acc);
        float px = pos[node * 3 + 0];
        float py = pos[node * 3 + 1];
        float pz = pos[node * 3 + 2];
        float pp = px * W1s[32 * 64 + k];
        pp = fmaf(py, W1s[33 * 64 + k], pp);
        pp = fmaf(pz, W1s[34 * 64 + k], pp);

        g_U[node * 64 + k] = acc + pp;
        out[gid] = -FLT_MAX;
    }
}

__device__ __forceinline__ void atomicMaxF(float* addr, float v) {
    if (v >= 0.0f) atomicMax((int*)addr, __float_as_int(v));
    else           atomicMin((unsigned int*)addr, __float_as_uint(v));
}

// ---------------------------------------------------------------------------
// Kernel 3: persistent scalar-FFMA2 edge kernel.
// 128 threads/CTA, 6 CTAs/SM, tile = 64 edges x 64 outputs.
// Gather phase computes P[dst] on the fly from pos[dst] (12B) and W1b
// (thread-invariant 12 floats, reloaded per tile via L1-hit LDGs) with the
// EXACT fmaf chain of the precompute — bit-identical to materialized P.
// Thread tile (GEMM) = 4 edges x 8 outputs (proven layout).
// ---------------------------------------------------------------------------
__global__ void __launch_bounds__(128, 6) edge_kernel(
    const float* __restrict__ pos,      // [n, 3]
    const float* __restrict__ W1,       // [35, 64]
    const float* __restrict__ W2,       // [64 k][64 n] row-major
    const float* __restrict__ b2,       // [64]
    float* __restrict__ out,            // [n, 64]
    int n, int E) {
    extern __shared__ float smem[];
    float* Hs  = smem;                       // TILE_E * H_STRIDE
    float* W2s = smem + TILE_E * H_STRIDE;   // 64 * 64
    float* b2s = W2s + 64 * 64;              // 64
    int*   dsts = (int*)(b2s + 64);          // TILE_E

    const int tid = threadIdx.x;
    // ---- Stage W2 + b2 once per persistent CTA ----
    for (int i = tid; i < 64 * 64; i += 128) W2s[i] = W2[i];
    if (tid < 64) b2s[tid] = b2[tid];
    __syncthreads();

    const int total = E + n;
    const int nTiles = (total + TILE_E - 1) / TILE_E;

    const int c  = tid & 15;   // float4 chunk of 64-wide row
    const int es = tid >> 4;   // 8 rows per pass
    const int cg = tid & 7;
    const int e0 = tid >> 3;        // 0..15
    const int kb1 = cg * 4;
    const int kb2 = 32 + cg * 4;
    const float4 bbA = *(const float4*)&b2s[kb1];
    const float4 bbB = *(const float4*)&b2s[kb2];

    for (int tile = blockIdx.x; tile < nTiles; tile += gridDim.x) {
        const int base = tile * TILE_E;

        // W1b columns for this thread's chunk (L1-hit after first tile;
        // loaded inside the tile loop to keep GEMM-phase reg pressure flat).
        const float4 wb0 = __ldg((const float4*)&W1[32 * 64 + c * 4]);
        const float4 wb1 = __ldg((const float4*)&W1[33 * 64 + c * 4]);
        const float4 wb2 = __ldg((const float4*)&W1[34 * 64 + c * 4]);

        // ---------------- Stage 1: gather + on-the-fly P + relu ----------
#pragma unroll
        for (int j = 0; j < TILE_E / 8; j++) {
            int el = j * 8 + es;
            int eg = base + el;
            float4 h = make_float4(0.f, 0.f, 0.f, 0.f);
            int d = -1;
            if (eg < total) {
                int s = g_SRC[eg];
                d = g_DST[eg];
                float4 u = *(const float4*)&g_U[s * 64 + c * 4];
                float px = __ldg(&pos[d * 3 + 0]);
                float py = __ldg(&pos[d * 3 + 1]);
                float pz = __ldg(&pos[d * 3 + 2]);
                // EXACT op order of precompute's pp chain (bit-identical).
                float p0 = px * wb0.x; p0 = fmaf(py, wb1.x, p0); p0 = fmaf(pz, wb2.x, p0);
                float p1 = px * wb0.y; p1 = fmaf(py, wb1.y, p1); p1 = fmaf(pz, wb2.y, p1);
                float p2 = px * wb0.z; p2 = fmaf(py, wb1.z, p2); p2 = fmaf(pz, wb2.z, p2);
                float p3 = px * wb0.w; p3 = fmaf(py, wb1.w, p3); p3 = fmaf(pz, wb2.w, p3);
                h.x = fmaxf(u.x - p0, 0.0f);
                h.y = fmaxf(u.y - p1, 0.0f);
                h.z = fmaxf(u.z - p2, 0.0f);
                h.w = fmaxf(u.w - p3, 0.0f);
            }
            if (c == 0) {
                dsts[el] = d;
                if (d >= 0) {
                    prefetchL2(out + (long long)d * 64);
                    prefetchL2(out + (long long)d * 64 + 32);
                }
            }
            *(float4*)&Hs[el * H_STRIDE + c * 4] = h;
        }
        __syncthreads();

        // ---------------- Stage 2: GEMM (4 edges x 8 cols / thread) -------
        unsigned long long acc[4][4];
#pragma unroll
        for (int i = 0; i < 4; i++)
#pragma unroll
            for (int jq = 0; jq < 4; jq++) acc[i][jq] = 0ull;

#pragma unroll
        for (int m4 = 0; m4 < 16; m4++) {
            float h0[4], h1[4], h2[4], h3[4];
            {
                float4 t;
                t = *(const float4*)&Hs[(e0 +  0) * H_STRIDE + m4 * 4];
                h0[0] = t.x; h0[1] = t.y; h0[2] = t.z; h0[3] = t.w;
                t = *(const float4*)&Hs[(e0 + 16) * H_STRIDE + m4 * 4];
                h1[0] = t.x; h1[1] = t.y; h1[2] = t.z; h1[3] = t.w;
                t = *(const float4*)&Hs[(e0 + 32) * H_STRIDE + m4 * 4];
                h2[0] = t.x; h2[1] = t.y; h2[2] = t.z; h2[3] = t.w;
                t = *(const float4*)&Hs[(e0 + 48) * H_STRIDE + m4 * 4];
                h3[0] = t.x; h3[1] = t.y; h3[2] = t.z; h3[3] = t.w;
            }
#pragma unroll
            for (int mm = 0; mm < 4; mm++) {
                const int m = m4 * 4 + mm;
                ulonglong2 wA = *(const ulonglong2*)&W2s[m * 64 + kb1];
                ulonglong2 wB = *(const ulonglong2*)&W2s[m * 64 + kb2];
                unsigned long long hb;
                hb = packdup(h0[mm]);
                ffma2(acc[0][0], hb, wA.x); ffma2(acc[0][1], hb, wA.y);
                ffma2(acc[0][2], hb, wB.x); ffma2(acc[0][3], hb, wB.y);
                hb = packdup(h1[mm]);
                ffma2(acc[1][0], hb, wA.x); ffma2(acc[1][1], hb, wA.y);
                ffma2(acc[1][2], hb, wB.x); ffma2(acc[1][3], hb, wB.y);
                hb = packdup(h2[mm]);
                ffma2(acc[2][0], hb, wA.x); ffma2(acc[2][1], hb, wA.y);
                ffma2(acc[2][2], hb, wB.x); ffma2(acc[2][3], hb, wB.y);
                hb = packdup(h3[mm]);
                ffma2(acc[3][0], hb, wA.x); ffma2(acc[3][1], hb, wA.y);
                ffma2(acc[3][2], hb, wB.x); ffma2(acc[3][3], hb, wB.y);
            }
        }

        // ---------------- Stage 3: scatter-max ----------------
#pragma unroll
        for (int i = 0; i < 4; i++) {
            int d = dsts[e0 + 16 * i];
            if (d < 0) continue;
            float v0, v1, v2, v3, v4, v5, v6, v7;
            unpack2(acc[i][0], v0, v1);
            unpack2(acc[i][1], v2, v3);
            unpack2(acc[i][2], v4, v5);
            unpack2(acc[i][3], v6, v7);
            v0 += bbA.x; v1 += bbA.y; v2 += bbA.z; v3 += bbA.w;
            v4 += bbB.x; v5 += bbB.y; v6 += bbB.z; v7 += bbB.w;
            float* oA = out + (long long)d * 64 + kb1;
            float* oB = out + (long long)d * 64 + kb2;
            float4 curA = *(const float4*)oA;
            float4 curB = *(const float4*)oB;
            if (v0 > curA.x) atomicMaxF(oA + 0, v0);
            if (v1 > curA.y) atomicMaxF(oA + 1, v1);
            if (v2 > curA.z) atomicMaxF(oA + 2, v2);
            if (v3 > curA.w) atomicMaxF(oA + 3, v3);
            if (v4 > curB.x) atomicMaxF(oB + 0, v4);
            if (v5 > curB.y) atomicMaxF(oB + 1, v5);
            if (v6 > curB.z) atomicMaxF(oB + 2, v6);
            if (v7 > curB.w) atomicMaxF(oB + 3, v7);
        }
        __syncthreads();   // H reuse safe for next tile
    }
}

// ---------------------------------------------------------------------------
// Launch
// ---------------------------------------------------------------------------
extern "C" void kernel_launch(void* const* d_in, const int* in_sizes, int n_in,
                              void* d_out, int out_size) {
    const float* x   = (const float*)d_in[0];    // [n, 32]
    const float* pos = (const float*)d_in[1];    // [n, 3]
    const void*  ei  = d_in[2];                  // [2, E] int64 or int32
    const float* W1  = (const float*)d_in[3];    // [35, 64]
    const float* b1  = (const float*)d_in[4];    // [64]
    const float* W2  = (const float*)d_in[5];    // [64, 64]
    const float* b2  = (const float*)d_in[6];    // [64]
    float*       out = (float*)d_out;            // [n, 64]

    int n = in_sizes[0] / D_FEAT;
    int E = in_sizes[2] / 2;

    const int smemBytes = (TILE_E * H_STRIDE + 64 * 64 + 64) * 4 + TILE_E * 4;
    cudaFuncSetAttribute(edge_kernel, cudaFuncAttributeMaxDynamicSharedMemorySize,
                         smemBytes);

    // 0) detect edge_index dtype, then normalize to int32 with self-loops
    detect_kernel<<<1, 256>>>((const long long*)ei, E, n);
    convert_edges_kernel<<<1480, 256>>>(ei, E, n);
    // 1) per-node precompute of U + out init (fused, grid-stride)
    precompute_kernel<<<1480, 256>>>(x, pos, W1, b1, out, n);
    // 2) persistent edge kernel: 6 CTAs/SM x 148 SMs
    edge_kernel<<<888, 128, smemBytes>>>(pos, W1, W2, b2, out, n, E);
}